// round 5
// baseline (speedup 1.0000x reference)
#include <cuda_runtime.h>

// ============================================================================
// Problem constants
// ============================================================================
static constexpr int N_NODES  = 10000;
static constexpr int N_EDGES  = 250000;
static constexpr int FEAT     = 288;   // 9 * F
static constexpr int F        = 32;
static constexpr int HIDDEN   = 64;
static constexpr int NPATH    = 11;
static constexpr int RADIAL   = NPATH * F;  // 352
static constexpr int EW       = 4;          // edges per warp
static_assert(N_EDGES % EW == 0, "edge tiling");

// ============================================================================
// Compile-time Wigner-3j construction (faithful port of the reference numpy)
// ============================================================================
#define HDC __host__ __device__ constexpr

HDC double cfact(int n) { double r = 1.0; for (int i = 2; i <= n; ++i) r *= (double)i; return r; }

HDC double csqrt(double x) {
    if (x <= 0.0) return 0.0;
    double g = (x > 1.0) ? x : 1.0;
    for (int i = 0; i < 40; ++i) g = 0.5 * (g + x / g);  // quadratic convergence; 40 >> enough
    return g;
}

HDC double su2_cg(int j1, int j2, int j3, int m1, int m2, int m3) {
    if (m1 + m2 != m3) return 0.0;
    double pref = csqrt((2.0 * j3 + 1.0) * cfact(j1 + j2 - j3) * cfact(j1 - j2 + j3) *
                        cfact(-j1 + j2 + j3) / cfact(j1 + j2 + j3 + 1));
    pref *= csqrt(cfact(j3 + m3) * cfact(j3 - m3) * cfact(j1 - m1) * cfact(j1 + m1) *
                  cfact(j2 - m2) * cfact(j2 + m2));
    double s = 0.0;
    for (int k = 0; k <= j1 + j2 - j3; ++k) {
        int d0 = k, d1 = j1 + j2 - j3 - k, d2 = j1 - m1 - k, d3 = j2 + m2 - k;
        int d4 = j3 - j2 + m1 + k, d5 = j3 - j1 - m2 + k;
        if (d0 < 0 || d1 < 0 || d2 < 0 || d3 < 0 || d4 < 0 || d5 < 0) continue;
        double term = 1.0 / (cfact(d0) * cfact(d1) * cfact(d2) * cfact(d3) * cfact(d4) * cfact(d5));
        s += (k & 1) ? -term : term;
    }
    return pref * s;
}

struct CD { double re, im; };
HDC CD cmul(CD a, CD b) { return CD{a.re * b.re - a.im * b.im, a.re * b.im + a.im * b.re}; }

struct Qm { CD v[5][5]; };
HDC Qm qmat(int l) {
    Qm q{};
    for (int i = 0; i < 5; ++i) for (int j = 0; j < 5; ++j) q.v[i][j] = CD{0.0, 0.0};
    const double inv = 1.0 / csqrt(2.0);
    for (int m = -l; m < 0; ++m) {
        q.v[l + m][l - m] = CD{inv, 0.0};    // q[l+m, l+|m|]
        q.v[l + m][l + m] = CD{0.0, -inv};   // q[l+m, l-|m|]
    }
    q.v[l][l] = CD{1.0, 0.0};
    for (int m = 1; m <= l; ++m) {
        const double sgn = (m & 1) ? -1.0 : 1.0;
        q.v[l + m][l + m] = CD{sgn * inv, 0.0};
        q.v[l + m][l - m] = CD{0.0, sgn * inv};
    }
    const CD ph = (l == 0) ? CD{1.0, 0.0} : ((l == 1) ? CD{0.0, -1.0} : CD{-1.0, 0.0}); // (-i)^l
    for (int i = 0; i < 2 * l + 1; ++i)
        for (int j = 0; j < 2 * l + 1; ++j) q.v[i][j] = cmul(ph, q.v[i][j]);
    return q;
}

// path prefactor: PATH_W[p] * (1 / sqrt(AVG_NEIGHBORS)) folded together
HDC double path_pref(int p) {
    // k per path: {0,1,2,1,0,2,1,2,1,0,2}; count(k=0)=3, count(k=1)=4, count(k=2)=4
    const int k = (p == 0 || p == 4 || p == 9) ? 0 : ((p == 1 || p == 3 || p == 6 || p == 8) ? 1 : 2);
    const double cnt = (k == 0) ? 3.0 : 4.0;
    return csqrt((2.0 * k + 1.0) / cnt) * 0.2; // 0.2 = 1/sqrt(25)
}

struct W3 { double v[5][5][5]; };
// Computes the reference _w3j(l1,l2,l3) and folds PATH_W[p]/sqrt(25) into it.
HDC W3 w3j_calc(int l1, int l2, int l3, int p) {
    W3 out{};
    double C[5][5][5] = {};
    for (int m1 = -l1; m1 <= l1; ++m1)
        for (int m2 = -l2; m2 <= l2; ++m2)
            for (int m3 = -l3; m3 <= l3; ++m3)
                C[l1 + m1][l2 + m2][l3 + m3] = su2_cg(l1, l2, l3, m1, m2, m3);
    const Qm q1 = qmat(l1), q2 = qmat(l2), q3 = qmat(l3);
    const int d1 = 2 * l1 + 1, d2 = 2 * l2 + 1, d3 = 2 * l3 + 1;
    double Wr[5][5][5] = {}, Wi[5][5][5] = {};
    for (int j = 0; j < d1; ++j)
        for (int l = 0; l < d2; ++l)
            for (int n = 0; n < d3; ++n) {
                CD acc{0.0, 0.0};
                for (int i = 0; i < d1; ++i)
                    for (int k = 0; k < d2; ++k)
                        for (int m = 0; m < d3; ++m) {
                            const double c = C[i][k][m];
                            if (c == 0.0) continue;
                            CD t = cmul(q1.v[i][j], q2.v[k][l]);
                            t = cmul(t, CD{q3.v[m][n].re, -q3.v[m][n].im});
                            acc.re += t.re * c;
                            acc.im += t.im * c;
                        }
                Wr[j][l][n] = acc.re;
                Wi[j][l][n] = acc.im;
            }
    double nr = 0.0, ni = 0.0;
    for (int j = 0; j < d1; ++j)
        for (int l = 0; l < d2; ++l)
            for (int n = 0; n < d3; ++n) { nr += Wr[j][l][n] * Wr[j][l][n]; ni += Wi[j][l][n] * Wi[j][l][n]; }
    const bool useR = (nr >= ni);
    const double scale = path_pref(p) / csqrt(useR ? nr : ni);
    for (int j = 0; j < d1; ++j)
        for (int l = 0; l < d2; ++l)
            for (int n = 0; n < d3; ++n)
                out.v[j][l][n] = (useR ? Wr[j][l][n] : Wi[j][l][n]) * scale;
    return out;
}

template <int I, int J, int K, int P>
struct WHold { static constexpr W3 W = w3j_calc(I, J, K, P); };
template <int I, int J, int K, int P> constexpr W3 WHold<I, J, K, P>::W;

// ============================================================================
// Compile-time 3D unroller so zero coefficients are eliminated at compile time
// ============================================================================
template <int N> struct Ic { static constexpr int v = N; };

template <int NA, int NB, int NC, int IDX, class Fn>
__device__ __forceinline__ void unr3(Fn&& f) {
    if constexpr (IDX < NA * NB * NC) {
        f(Ic<IDX / (NB * NC)>{}, Ic<(IDX / NC) % NB>{}, Ic<IDX % NC>{});
        unr3<NA, NB, NC, IDX + 1>(f);
    }
}

template <int I, int J, int K, int P>
__device__ __forceinline__ void apply_path(const float (&xi)[2 * I + 1],
                                           const float (&yj)[2 * J + 1],
                                           float rw,
                                           float (&ok)[2 * K + 1]) {
    unr3<2 * I + 1, 2 * J + 1, 2 * K + 1, 0>([&](auto A, auto B, auto C) {
        constexpr double wv = WHold<I, J, K, P>::W.v[decltype(A)::v][decltype(B)::v][decltype(C)::v];
        if constexpr (wv > 1e-7 || wv < -1e-7) {   // drop structural zeros (incl. roundoff dust)
            ok[decltype(C)::v] =
                fmaf((float)wv * (xi[decltype(A)::v] * yj[decltype(B)::v]), rw, ok[decltype(C)::v]);
        }
    });
}

// ============================================================================
// Main fused kernel: one warp = EW edges, one lane = one feature channel
// ============================================================================
__global__ void __launch_bounds__(256)
conv_kernel(const float* __restrict__ nodes, const float* __restrict__ pos,
            const int* __restrict__ src, const int* __restrict__ dst,
            const float* __restrict__ w1, const float* __restrict__ b1,
            const float* __restrict__ w2, const float* __restrict__ b2,
            float* __restrict__ out) {
    const int lane = threadIdx.x & 31;
    const int g = (int)((blockIdx.x * blockDim.x + threadIdx.x) >> 5);
    constexpr int NGROUPS = N_EDGES / EW;
    if (g >= NGROUPS) return;
    const int e0 = g * EW;

    // loop-invariant weights: lane owns hidden channels {lane, lane+32}
    float w1a[8], w1b[8];
#pragma unroll
    for (int n = 0; n < 8; ++n) {
        w1a[n] = w1[n * HIDDEN + lane];
        w1b[n] = w1[n * HIDDEN + 32 + lane];
    }
    const float b1a = b1[lane], b1b = b1[lane + 32];
    float b2r[NPATH];
#pragma unroll
    for (int t = 0; t < NPATH; ++t) b2r[t] = b2[t * 32 + lane];

    int esrc[EW], edst[EW];
    float eux[EW], euy[EW], euz[EW], ecut[EW];
    float hlo[EW], hhi[EW];

    constexpr float PI = 3.14159265358979323846f;
#pragma unroll
    for (int q = 0; q < EW; ++q) {
        const int e = e0 + q;
        const int s = src[e], d = dst[e];
        esrc[q] = s; edst[q] = d;
        const float dx = pos[3 * s + 0] - pos[3 * d + 0];
        const float dy = pos[3 * s + 1] - pos[3 * d + 1];
        const float dz = pos[3 * s + 2] - pos[3 * d + 2];
        const float dist = sqrtf(dx * dx + dy * dy + dz * dz);

        // polynomial cutoff (RCUT = 4)
        const float u = dist * 0.25f;
        const float u2 = u * u;
        const float u5 = u2 * u2 * u;
        float cut = 1.0f - 6.0f * u5 + 5.0f * u5 * u;
        ecut[q] = (dist < 4.0f) ? cut : 0.0f;

        const float invd = 1.0f / fmaxf(dist, 1e-12f);
        eux[q] = dx * invd; euy[q] = dy * invd; euz[q] = dz * invd;

        // bessel basis (BESSEL_END = 5): sin(n*pi*t) via Chebyshev recurrence
        const float t = dist * 0.2f;
        float sp, cp;
        sincosf(PI * t, &sp, &cp);
        const float mask = (t > 0.0f && t < 1.0f) ? 1.0f : 0.0f;
        const float inv_t = (t > 0.0f) ? (1.0f / t) : 1.0f;
        const float coef = 0.6324555320336759f * inv_t * mask; // sqrt(2/5)/t * mask
        float acc_lo = b1a, acc_hi = b1b;
        float s_prev = 0.0f, s_cur = sp;
        const float c2 = 2.0f * cp;
#pragma unroll
        for (int n = 0; n < 8; ++n) {
            const float bn = coef * s_cur;
            acc_lo = fmaf(bn, w1a[n], acc_lo);
            acc_hi = fmaf(bn, w1b[n], acc_hi);
            const float s_next = c2 * s_cur - s_prev;
            s_prev = s_cur; s_cur = s_next;
        }
        hlo[q] = acc_lo / (1.0f + __expf(-acc_lo));  // silu
        hhi[q] = acc_hi / (1.0f + __expf(-acc_hi));
    }

    // layer 2: radial[c] = sum_k h[k] * w2[k][c], c = t*32 + lane (coalesced)
    float racc[EW][NPATH];
#pragma unroll
    for (int q = 0; q < EW; ++q)
#pragma unroll
        for (int t = 0; t < NPATH; ++t) racc[q][t] = 0.0f;

#pragma unroll 2
    for (int k = 0; k < HIDDEN; ++k) {
        const float* wr = w2 + k * RADIAL + lane;
        float wv[NPATH];
#pragma unroll
        for (int t = 0; t < NPATH; ++t) wv[t] = __ldg(wr + t * 32);
#pragma unroll
        for (int q = 0; q < EW; ++q) {
            const float hv = (k < 32) ? hlo[q] : hhi[q];
            const float hk = __shfl_sync(0xffffffffu, hv, k & 31);
#pragma unroll
            for (int t = 0; t < NPATH; ++t) racc[q][t] = fmaf(hk, wv[t], racc[q][t]);
        }
    }

    // tensor product + atomic scatter, channel u = lane
#pragma unroll
    for (int q = 0; q < EW; ++q) {
        const float* nb = nodes + esrc[q] * FEAT;
        float x0[1] = { nb[lane] };
        float x1[3], x2[5];
#pragma unroll
        for (int a = 0; a < 3; ++a) x1[a] = nb[32 + 3 * lane + a];
#pragma unroll
        for (int a = 0; a < 5; ++a) x2[a] = nb[128 + 5 * lane + a];

        const float ux = eux[q], uy = euy[q], uz = euz[q];
        constexpr float S3   = 1.7320508075688772f;  // sqrt(3)
        constexpr float S15  = 3.8729833462074170f;  // sqrt(15)
        constexpr float S5H  = 1.1180339887498949f;  // sqrt(5)/2
        constexpr float S15H = 1.9364916731037085f;  // sqrt(15)/2
        float y0[1] = { 1.0f };
        float y1[3] = { S3 * uy, S3 * uz, S3 * ux };
        float y2[5] = { S15 * ux * uy, S15 * uy * uz, S5H * (3.0f * uz * uz - 1.0f),
                        S15 * ux * uz, S15H * (ux * ux - uy * uy) };

        float rw[NPATH];
#pragma unroll
        for (int t = 0; t < NPATH; ++t) rw[t] = (racc[q][t] + b2r[t]) * ecut[q];

        float o0[1] = {0.0f};
        float o1[3] = {0.0f, 0.0f, 0.0f};
        float o2[5] = {0.0f, 0.0f, 0.0f, 0.0f, 0.0f};
        apply_path<0, 0, 0, 0>(x0, y0, rw[0], o0);
        apply_path<0, 1, 1, 1>(x0, y1, rw[1], o1);
        apply_path<0, 2, 2, 2>(x0, y2, rw[2], o2);
        apply_path<1, 0, 1, 3>(x1, y0, rw[3], o1);
        apply_path<1, 1, 0, 4>(x1, y1, rw[4], o0);
        apply_path<1, 1, 2, 5>(x1, y1, rw[5], o2);
        apply_path<1, 2, 1, 6>(x1, y2, rw[6], o1);
        apply_path<2, 0, 2, 7>(x2, y0, rw[7], o2);
        apply_path<2, 1, 1, 8>(x2, y1, rw[8], o1);
        apply_path<2, 2, 0, 9>(x2, y2, rw[9], o0);
        apply_path<2, 2, 2, 10>(x2, y2, rw[10], o2);

        float* ob = out + edst[q] * FEAT;
        atomicAdd(ob + lane, o0[0]);
#pragma unroll
        for (int c = 0; c < 3; ++c) atomicAdd(ob + 32 + 3 * lane + c, o1[c]);
#pragma unroll
        for (int c = 0; c < 5; ++c) atomicAdd(ob + 128 + 5 * lane + c, o2[c]);
    }
}

// ============================================================================
// Launch: zero output (poisoned by harness), then fused edge kernel.
// Graph-capturable: one memset + one kernel, no alloc, no sync.
// ============================================================================
extern "C" void kernel_launch(void* const* d_in, const int* in_sizes, int n_in,
                              void* d_out, int out_size) {
    (void)in_sizes; (void)n_in;
    const float* nodes = (const float*)d_in[0];
    const float* pos   = (const float*)d_in[1];
    const int*   src   = (const int*)d_in[2];
    const int*   dst   = (const int*)d_in[3];
    const float* w1    = (const float*)d_in[4];
    const float* b1    = (const float*)d_in[5];
    const float* w2    = (const float*)d_in[6];
    const float* b2    = (const float*)d_in[7];
    float* out = (float*)d_out;

    cudaMemsetAsync(out, 0, (size_t)out_size * sizeof(float), 0);

    constexpr int NGROUPS = N_EDGES / EW;           // 62500 warps of work
    constexpr int WARPS_PER_BLOCK = 8;              // 256 threads
    const int blocks = (NGROUPS + WARPS_PER_BLOCK - 1) / WARPS_PER_BLOCK;
    conv_kernel<<<blocks, WARPS_PER_BLOCK * 32>>>(nodes, pos, src, dst, w1, b1, w2, b2, out);
}

// round 6
// speedup vs baseline: 2.0229x; 2.0229x over previous
#include <cuda_runtime.h>

// ============================================================================
// Problem constants
// ============================================================================
static constexpr int N_NODES  = 10000;
static constexpr int N_EDGES  = 250000;
static constexpr int FEAT     = 288;   // 9 * F
static constexpr int F        = 32;
static constexpr int HIDDEN   = 64;
static constexpr int NPATH    = 11;
static constexpr int RADIAL   = NPATH * F;  // 352
static constexpr int EW       = 4;          // edges per warp
static_assert(N_EDGES % EW == 0, "edge tiling");

// ============================================================================
// Compile-time Wigner-3j construction (faithful port of the reference numpy)
// ============================================================================
#define HDC __host__ __device__ constexpr

HDC double cfact(int n) { double r = 1.0; for (int i = 2; i <= n; ++i) r *= (double)i; return r; }

HDC double csqrt(double x) {
    if (x <= 0.0) return 0.0;
    double g = (x > 1.0) ? x : 1.0;
    for (int i = 0; i < 40; ++i) g = 0.5 * (g + x / g);
    return g;
}

HDC double su2_cg(int j1, int j2, int j3, int m1, int m2, int m3) {
    if (m1 + m2 != m3) return 0.0;
    double pref = csqrt((2.0 * j3 + 1.0) * cfact(j1 + j2 - j3) * cfact(j1 - j2 + j3) *
                        cfact(-j1 + j2 + j3) / cfact(j1 + j2 + j3 + 1));
    pref *= csqrt(cfact(j3 + m3) * cfact(j3 - m3) * cfact(j1 - m1) * cfact(j1 + m1) *
                  cfact(j2 - m2) * cfact(j2 + m2));
    double s = 0.0;
    for (int k = 0; k <= j1 + j2 - j3; ++k) {
        int d0 = k, d1 = j1 + j2 - j3 - k, d2 = j1 - m1 - k, d3 = j2 + m2 - k;
        int d4 = j3 - j2 + m1 + k, d5 = j3 - j1 - m2 + k;
        if (d0 < 0 || d1 < 0 || d2 < 0 || d3 < 0 || d4 < 0 || d5 < 0) continue;
        double term = 1.0 / (cfact(d0) * cfact(d1) * cfact(d2) * cfact(d3) * cfact(d4) * cfact(d5));
        s += (k & 1) ? -term : term;
    }
    return pref * s;
}

struct CD { double re, im; };
HDC CD cmul(CD a, CD b) { return CD{a.re * b.re - a.im * b.im, a.re * b.im + a.im * b.re}; }

struct Qm { CD v[5][5]; };
HDC Qm qmat(int l) {
    Qm q{};
    for (int i = 0; i < 5; ++i) for (int j = 0; j < 5; ++j) q.v[i][j] = CD{0.0, 0.0};
    const double inv = 1.0 / csqrt(2.0);
    for (int m = -l; m < 0; ++m) {
        q.v[l + m][l - m] = CD{inv, 0.0};
        q.v[l + m][l + m] = CD{0.0, -inv};
    }
    q.v[l][l] = CD{1.0, 0.0};
    for (int m = 1; m <= l; ++m) {
        const double sgn = (m & 1) ? -1.0 : 1.0;
        q.v[l + m][l + m] = CD{sgn * inv, 0.0};
        q.v[l + m][l - m] = CD{0.0, sgn * inv};
    }
    const CD ph = (l == 0) ? CD{1.0, 0.0} : ((l == 1) ? CD{0.0, -1.0} : CD{-1.0, 0.0}); // (-i)^l
    for (int i = 0; i < 2 * l + 1; ++i)
        for (int j = 0; j < 2 * l + 1; ++j) q.v[i][j] = cmul(ph, q.v[i][j]);
    return q;
}

// path prefactor: PATH_W[p] * (1 / sqrt(AVG_NEIGHBORS)) folded together
HDC double path_pref(int p) {
    const int k = (p == 0 || p == 4 || p == 9) ? 0 : ((p == 1 || p == 3 || p == 6 || p == 8) ? 1 : 2);
    const double cnt = (k == 0) ? 3.0 : 4.0;
    return csqrt((2.0 * k + 1.0) / cnt) * 0.2;
}

struct W3 { double v[5][5][5]; };
HDC W3 w3j_calc(int l1, int l2, int l3, int p) {
    W3 out{};
    double C[5][5][5] = {};
    for (int m1 = -l1; m1 <= l1; ++m1)
        for (int m2 = -l2; m2 <= l2; ++m2)
            for (int m3 = -l3; m3 <= l3; ++m3)
                C[l1 + m1][l2 + m2][l3 + m3] = su2_cg(l1, l2, l3, m1, m2, m3);
    const Qm q1 = qmat(l1), q2 = qmat(l2), q3 = qmat(l3);
    const int d1 = 2 * l1 + 1, d2 = 2 * l2 + 1, d3 = 2 * l3 + 1;
    double Wr[5][5][5] = {}, Wi[5][5][5] = {};
    for (int j = 0; j < d1; ++j)
        for (int l = 0; l < d2; ++l)
            for (int n = 0; n < d3; ++n) {
                CD acc{0.0, 0.0};
                for (int i = 0; i < d1; ++i)
                    for (int k = 0; k < d2; ++k)
                        for (int m = 0; m < d3; ++m) {
                            const double c = C[i][k][m];
                            if (c == 0.0) continue;
                            CD t = cmul(q1.v[i][j], q2.v[k][l]);
                            t = cmul(t, CD{q3.v[m][n].re, -q3.v[m][n].im});
                            acc.re += t.re * c;
                            acc.im += t.im * c;
                        }
                Wr[j][l][n] = acc.re;
                Wi[j][l][n] = acc.im;
            }
    double nr = 0.0, ni = 0.0;
    for (int j = 0; j < d1; ++j)
        for (int l = 0; l < d2; ++l)
            for (int n = 0; n < d3; ++n) { nr += Wr[j][l][n] * Wr[j][l][n]; ni += Wi[j][l][n] * Wi[j][l][n]; }
    const bool useR = (nr >= ni);
    const double scale = path_pref(p) / csqrt(useR ? nr : ni);
    for (int j = 0; j < d1; ++j)
        for (int l = 0; l < d2; ++l)
            for (int n = 0; n < d3; ++n)
                out.v[j][l][n] = (useR ? Wr[j][l][n] : Wi[j][l][n]) * scale;
    return out;
}

template <int I, int J, int K, int P>
struct WHold { static constexpr W3 W = w3j_calc(I, J, K, P); };
template <int I, int J, int K, int P> constexpr W3 WHold<I, J, K, P>::W;

// ============================================================================
// Compile-time 3D unroller (structural zeros eliminated at compile time)
// ============================================================================
template <int N> struct Ic { static constexpr int v = N; };

template <int NA, int NB, int NC, int IDX, class Fn>
__device__ __forceinline__ void unr3(Fn&& f) {
    if constexpr (IDX < NA * NB * NC) {
        f(Ic<IDX / (NB * NC)>{}, Ic<(IDX / NC) % NB>{}, Ic<IDX % NC>{});
        unr3<NA, NB, NC, IDX + 1>(f);
    }
}

template <int I, int J, int K, int P>
__device__ __forceinline__ void apply_path(const float (&xi)[2 * I + 1],
                                           const float (&yj)[2 * J + 1],
                                           float rw,
                                           float (&ok)[2 * K + 1]) {
    unr3<2 * I + 1, 2 * J + 1, 2 * K + 1, 0>([&](auto A, auto B, auto C) {
        constexpr double wv = WHold<I, J, K, P>::W.v[decltype(A)::v][decltype(B)::v][decltype(C)::v];
        if constexpr (wv > 1e-7 || wv < -1e-7) {
            ok[decltype(C)::v] =
                fmaf((float)wv * (xi[decltype(A)::v] * yj[decltype(B)::v]), rw, ok[decltype(C)::v]);
        }
    });
}

// ============================================================================
// f32x2 packed-FMA helpers (ptxas never auto-fuses; PTX fma.rn.f32x2 required)
// ============================================================================
__device__ __forceinline__ unsigned long long pack2(float lo, float hi) {
    unsigned long long r;
    asm("mov.b64 %0, {%1, %2};" : "=l"(r) : "f"(lo), "f"(hi));
    return r;
}
__device__ __forceinline__ void unpack2(unsigned long long v, float& lo, float& hi) {
    asm("mov.b64 {%0, %1}, %2;" : "=f"(lo), "=f"(hi) : "l"(v));
}
__device__ __forceinline__ unsigned long long ffma2(unsigned long long a, unsigned long long b,
                                                    unsigned long long c) {
    unsigned long long d;
    asm("fma.rn.f32x2 %0, %1, %2, %3;" : "=l"(d) : "l"(a), "l"(b), "l"(c));
    return d;
}

// ============================================================================
// Main fused kernel: one warp = EW edges, one lane = one feature channel
// ============================================================================
__global__ void __launch_bounds__(128, 5)
conv_kernel(const float* __restrict__ nodes, const float* __restrict__ pos,
            const int* __restrict__ src, const int* __restrict__ dst,
            const float* __restrict__ w1, const float* __restrict__ b1,
            const float* __restrict__ w2, const float* __restrict__ b2,
            float* __restrict__ out) {
    const int lane = threadIdx.x & 31;
    const int g = (int)((blockIdx.x * blockDim.x + threadIdx.x) >> 5);
    constexpr int NGROUPS = N_EDGES / EW;
    if (g >= NGROUPS) return;
    const int e0 = g * EW;

    int esrc[EW], edst[EW];
    float eux[EW], euy[EW], euz[EW], ecut[EW];
    float hlo[EW], hhi[EW];

    constexpr float PI = 3.14159265358979323846f;
    {
        // layer-1 weights for this lane's two hidden channels (dead after this block)
        float w1a[8], w1b[8];
#pragma unroll
        for (int n = 0; n < 8; ++n) {
            w1a[n] = w1[n * HIDDEN + lane];
            w1b[n] = w1[n * HIDDEN + 32 + lane];
        }
        const float b1a = b1[lane], b1b = b1[lane + 32];

#pragma unroll
        for (int q = 0; q < EW; ++q) {
            const int e = e0 + q;
            const int s = src[e], d = dst[e];
            esrc[q] = s; edst[q] = d;
            const float dx = pos[3 * s + 0] - pos[3 * d + 0];
            const float dy = pos[3 * s + 1] - pos[3 * d + 1];
            const float dz = pos[3 * s + 2] - pos[3 * d + 2];
            const float dist = sqrtf(dx * dx + dy * dy + dz * dz);

            // polynomial cutoff (RCUT = 4)
            const float u = dist * 0.25f;
            const float u2 = u * u;
            const float u5 = u2 * u2 * u;
            const float cut = 1.0f - 6.0f * u5 + 5.0f * u5 * u;
            ecut[q] = (dist < 4.0f) ? cut : 0.0f;

            const float invd = __fdividef(1.0f, fmaxf(dist, 1e-12f));
            eux[q] = dx * invd; euy[q] = dy * invd; euz[q] = dz * invd;

            // bessel basis (BESSEL_END=5): sin(n*pi*t) via Chebyshev recurrence
            const float t = dist * 0.2f;
            float sp, cp;
            __sincosf(PI * t, &sp, &cp);           // fast path; |err| ~1e-6 on (0, pi)
            const float mask = (t > 0.0f && t < 1.0f) ? 1.0f : 0.0f;
            const float inv_t = (t > 0.0f) ? __fdividef(1.0f, t) : 1.0f;
            const float coef = 0.6324555320336759f * inv_t * mask; // sqrt(2/5)/t * mask
            float acc_lo = b1a, acc_hi = b1b;
            float s_prev = 0.0f, s_cur = sp;
            const float c2 = 2.0f * cp;
#pragma unroll
            for (int n = 0; n < 8; ++n) {
                const float bn = coef * s_cur;
                acc_lo = fmaf(bn, w1a[n], acc_lo);
                acc_hi = fmaf(bn, w1b[n], acc_hi);
                const float s_next = c2 * s_cur - s_prev;
                s_prev = s_cur; s_cur = s_next;
            }
            hlo[q] = __fdividef(acc_lo, 1.0f + __expf(-acc_lo));  // silu
            hhi[q] = __fdividef(acc_hi, 1.0f + __expf(-acc_hi));
        }
    }

    // ------------------------------------------------------------------------
    // layer 2: radial[c] = b2[c] + sum_k h[k]*w2[k][c], c = t*32+lane.
    // Accumulate path-pairs as packed f32x2 (FFMA2), path 10 as scalar.
    // ------------------------------------------------------------------------
    unsigned long long racc2[EW][5];
    float racc1[EW];
#pragma unroll
    for (int j = 0; j < 5; ++j) {
        const unsigned long long bp = pack2(b2[(2 * j) * 32 + lane], b2[(2 * j + 1) * 32 + lane]);
#pragma unroll
        for (int q = 0; q < EW; ++q) racc2[q][j] = bp;
    }
    {
        const float b10 = b2[10 * 32 + lane];
#pragma unroll
        for (int q = 0; q < EW; ++q) racc1[q] = b10;
    }

#pragma unroll 2
    for (int k = 0; k < HIDDEN; ++k) {
        const float* wr = w2 + k * RADIAL + lane;
        float wv[NPATH];
#pragma unroll
        for (int t = 0; t < NPATH; ++t) wv[t] = __ldg(wr + t * 32);
        unsigned long long wp[5];
#pragma unroll
        for (int j = 0; j < 5; ++j) wp[j] = pack2(wv[2 * j], wv[2 * j + 1]);
#pragma unroll
        for (int q = 0; q < EW; ++q) {
            const float hv = (k < 32) ? hlo[q] : hhi[q];
            const float hk = __shfl_sync(0xffffffffu, hv, k & 31);
            const unsigned long long h2 = pack2(hk, hk);
#pragma unroll
            for (int j = 0; j < 5; ++j) racc2[q][j] = ffma2(wp[j], h2, racc2[q][j]);
            racc1[q] = fmaf(hk, wv[10], racc1[q]);
        }
    }

    // ------------------------------------------------------------------------
    // tensor product + atomic scatter, channel u = lane
    // ------------------------------------------------------------------------
#pragma unroll
    for (int q = 0; q < EW; ++q) {
        const float* nb = nodes + esrc[q] * FEAT;
        float x0[1] = { nb[lane] };
        float x1[3], x2[5];
#pragma unroll
        for (int a = 0; a < 3; ++a) x1[a] = nb[32 + 3 * lane + a];
#pragma unroll
        for (int a = 0; a < 5; ++a) x2[a] = nb[128 + 5 * lane + a];

        const float ux = eux[q], uy = euy[q], uz = euz[q];
        constexpr float S3   = 1.7320508075688772f;
        constexpr float S15  = 3.8729833462074170f;
        constexpr float S5H  = 1.1180339887498949f;
        constexpr float S15H = 1.9364916731037085f;
        float y0[1] = { 1.0f };
        float y1[3] = { S3 * uy, S3 * uz, S3 * ux };
        float y2[5] = { S15 * ux * uy, S15 * uy * uz, S5H * (3.0f * uz * uz - 1.0f),
                        S15 * ux * uz, S15H * (ux * ux - uy * uy) };

        float rw[NPATH];
#pragma unroll
        for (int j = 0; j < 5; ++j) {
            float lo, hi;
            unpack2(racc2[q][j], lo, hi);
            rw[2 * j]     = lo * ecut[q];
            rw[2 * j + 1] = hi * ecut[q];
        }
        rw[10] = racc1[q] * ecut[q];

        float o0[1] = {0.0f};
        float o1[3] = {0.0f, 0.0f, 0.0f};
        float o2[5] = {0.0f, 0.0f, 0.0f, 0.0f, 0.0f};
        apply_path<0, 0, 0, 0>(x0, y0, rw[0], o0);
        apply_path<0, 1, 1, 1>(x0, y1, rw[1], o1);
        apply_path<0, 2, 2, 2>(x0, y2, rw[2], o2);
        apply_path<1, 0, 1, 3>(x1, y0, rw[3], o1);
        apply_path<1, 1, 0, 4>(x1, y1, rw[4], o0);
        apply_path<1, 1, 2, 5>(x1, y1, rw[5], o2);
        apply_path<1, 2, 1, 6>(x1, y2, rw[6], o1);
        apply_path<2, 0, 2, 7>(x2, y0, rw[7], o2);
        apply_path<2, 1, 1, 8>(x2, y1, rw[8], o1);
        apply_path<2, 2, 0, 9>(x2, y2, rw[9], o0);
        apply_path<2, 2, 2, 10>(x2, y2, rw[10], o2);

        float* ob = out + edst[q] * FEAT;
        atomicAdd(ob + lane, o0[0]);
#pragma unroll
        for (int c = 0; c < 3; ++c) atomicAdd(ob + 32 + 3 * lane + c, o1[c]);
#pragma unroll
        for (int c = 0; c < 5; ++c) atomicAdd(ob + 128 + 5 * lane + c, o2[c]);
    }
}

// ============================================================================
// Launch: zero output (poisoned by harness), then fused edge kernel.
// ============================================================================
extern "C" void kernel_launch(void* const* d_in, const int* in_sizes, int n_in,
                              void* d_out, int out_size) {
    (void)in_sizes; (void)n_in;
    const float* nodes = (const float*)d_in[0];
    const float* pos   = (const float*)d_in[1];
    const int*   src   = (const int*)d_in[2];
    const int*   dst   = (const int*)d_in[3];
    const float* w1    = (const float*)d_in[4];
    const float* b1    = (const float*)d_in[5];
    const float* w2    = (const float*)d_in[6];
    const float* b2    = (const float*)d_in[7];
    float* out = (float*)d_out;

    cudaMemsetAsync(out, 0, (size_t)out_size * sizeof(float), 0);

    constexpr int NGROUPS = N_EDGES / EW;           // 62500 warps of work
    constexpr int THREADS = 128;                    // 4 warps/block
    const int blocks = (NGROUPS * 32 + THREADS - 1) / THREADS;
    conv_kernel<<<blocks, THREADS>>>(nodes, pos, src, dst, w1, b1, w2, b2, out);
}